// round 8
// baseline (speedup 1.0000x reference)
#include <cuda_runtime.h>
#include <cuda_bf16.h>
#include <cstdint>

#define N_NODES 100000
#define N_EDGES 1600000
#define N_GRAPHS 1024
#define SCAN_BLOCKS ((N_NODES + 1023) / 1024)  // 98

// ---------------- scratch (static __device__; no allocation) ----------------
__device__ int   g_is64;            // 1 if integer inputs are int64, 0 if int32
__device__ int   g_src[N_EDGES];
__device__ int   g_dst[N_EDGES];
__device__ int   g_cnt[N_NODES];
__device__ int   g_ptr[N_NODES + 1];
__device__ int   g_fill[N_NODES];
__device__ int   g_srcbuf[N_EDGES];
__device__ float g_deginv[N_NODES];
__device__ int   g_gcnt[N_GRAPHS];
__device__ int   g_gptr[N_GRAPHS + 1];
__device__ int   g_bsum[SCAN_BLOCKS];
__device__ int   g_boff[SCAN_BLOCKS];
__device__ float g_aggx[N_NODES * 64];
__device__ float g_hbuf[(size_t)N_NODES * 128];
__device__ float g_ybuf[(size_t)N_NODES * 128];
__device__ float g_pool[N_GRAPHS * 64];

// compile-time buffer selector: 0 = g_aggx, 1 = g_hbuf, 2 = g_ybuf, 3 = external
template <int SEL>
__device__ __forceinline__ float* gbuf(const float* ext) {
    if (SEL == 0) return g_aggx;
    if (SEL == 1) return g_hbuf;
    if (SEL == 2) return g_ybuf;
    return (float*)ext;
}

__device__ __forceinline__ int clampN(int v, int n) {
    return ((unsigned)v < (unsigned)n) ? v : 0;
}

// ---------------- packed f32x2 helpers ----------------
__device__ __forceinline__ unsigned long long pk2(float x, float y) {
    unsigned long long r;
    asm("mov.b64 %0, {%1, %2};" : "=l"(r) : "f"(x), "f"(y));
    return r;
}
__device__ __forceinline__ void upk2(unsigned long long v, float& x, float& y) {
    asm("mov.b64 {%0, %1}, %2;" : "=f"(x), "=f"(y) : "l"(v));
}
__device__ __forceinline__ void ffma2(unsigned long long& acc, unsigned long long a,
                                      unsigned long long b) {
    asm("fma.rn.f32x2 %0, %1, %2, %0;" : "+l"(acc) : "l"(a), "l"(b));
}

// ---------------- zero + dtype detect (fused) ----------------
__global__ void k_zero(const unsigned int* __restrict__ ei_raw) {
    int i = blockIdx.x * blockDim.x + threadIdx.x;
    if (i < N_NODES) g_cnt[i] = 0;
    if (i < N_GRAPHS) g_gcnt[i] = 0;
    if (i == 0) {
        int is64 = 1;
        for (int t = 0; t < 128; t++) {
            if (ei_raw[2 * t + 1] != 0u) { is64 = 0; break; }
        }
        g_is64 = is64;
    }
}

__global__ void k_cvt_count(const void* __restrict__ ei, const void* __restrict__ batch) {
    int i = blockIdx.x * blockDim.x + threadIdx.x;
    int is64 = g_is64;
    if (i < N_EDGES) {
        int s, d;
        if (is64) {
            s = (int)((const long long*)ei)[i];
            d = (int)((const long long*)ei)[N_EDGES + i];
        } else {
            s = ((const int*)ei)[i];
            d = ((const int*)ei)[N_EDGES + i];
        }
        s = clampN(s, N_NODES);
        d = clampN(d, N_NODES);
        g_src[i] = s;
        g_dst[i] = d;
        atomicAdd(&g_cnt[d], 1);
    }
    if (i < N_NODES) {
        int b = is64 ? (int)((const long long*)batch)[i] : ((const int*)batch)[i];
        atomicAdd(&g_gcnt[clampN(b, N_GRAPHS)], 1);
    }
}

// ---------------- parallel 3-pass scan ----------------
__global__ void k_scanA() {
    __shared__ int wsum[32];
    __shared__ int woff[32];
    int tid = threadIdx.x, lane = tid & 31, wid = tid >> 5;
    int i = blockIdx.x * 1024 + tid;
    int c = (i < N_NODES) ? g_cnt[i] : 0;
    int incl = c;
    #pragma unroll
    for (int o = 1; o < 32; o <<= 1) {
        int v = __shfl_up_sync(0xffffffffu, incl, o);
        if (lane >= o) incl += v;
    }
    if (lane == 31) wsum[wid] = incl;
    __syncthreads();
    if (wid == 0) {
        int v = wsum[lane];
        int s = v;
        #pragma unroll
        for (int o = 1; o < 32; o <<= 1) {
            int t = __shfl_up_sync(0xffffffffu, s, o);
            if (lane >= o) s += t;
        }
        woff[lane] = s - v;
        if (lane == 31) wsum[0] = s;
    }
    __syncthreads();
    int excl = woff[wid] + (incl - c);
    if (i < N_NODES) g_ptr[i] = excl;
    if (tid == 0) g_bsum[blockIdx.x] = wsum[0];
}

__global__ void k_scanB() {
    __shared__ int wsum[32];
    int tid = threadIdx.x, lane = tid & 31, wid = tid >> 5;
    if (wid == 0) {
        int carry = 0;
        for (int base = 0; base < SCAN_BLOCKS; base += 32) {
            int idx = base + lane;
            int v = (idx < SCAN_BLOCKS) ? g_bsum[idx] : 0;
            int s = v;
            #pragma unroll
            for (int o = 1; o < 32; o <<= 1) {
                int t = __shfl_up_sync(0xffffffffu, s, o);
                if (lane >= o) s += t;
            }
            if (idx < SCAN_BLOCKS) g_boff[idx] = carry + s - v;
            carry += __shfl_sync(0xffffffffu, s, 31);
        }
        if (lane == 0) g_ptr[N_NODES] = carry;
    }
    __syncthreads();
    {
        int c = g_gcnt[tid];
        int incl = c;
        #pragma unroll
        for (int o = 1; o < 32; o <<= 1) {
            int v = __shfl_up_sync(0xffffffffu, incl, o);
            if (lane >= o) incl += v;
        }
        if (lane == 31) wsum[wid] = incl;
        __syncthreads();
        if (wid == 0) {
            int v = wsum[lane];
            int s = v;
            #pragma unroll
            for (int o = 1; o < 32; o <<= 1) {
                int t = __shfl_up_sync(0xffffffffu, s, o);
                if (lane >= o) s += t;
            }
            wsum[lane] = s - v;
        }
        __syncthreads();
        int excl = wsum[wid] + (incl - c);
        g_gptr[tid] = excl;
        if (tid == 1023) g_gptr[N_GRAPHS] = excl + c;
    }
}

__global__ void k_scanC() {
    int i = blockIdx.x * blockDim.x + threadIdx.x;
    if (i < N_NODES) {
        int p = g_ptr[i] + g_boff[i >> 10];
        g_ptr[i] = p;
        g_fill[i] = p;
        int c = g_cnt[i];
        g_deginv[i] = 1.0f / (float)(c > 0 ? c : 1);
    }
}

__global__ void k_fill() {
    int e = blockIdx.x * blockDim.x + threadIdx.x;
    if (e < N_EDGES) {
        int p = atomicAdd(&g_fill[g_dst[e]], 1);
        g_srcbuf[clampN(p, N_EDGES)] = g_src[e];
    }
}

// ---------------- aggregation: warp per node, half-warp per edge, float4 lanes ----------
template <int LDY, bool COMBINE, int YSEL, int OSEL>
__global__ void k_agg(const float* __restrict__ extY, const float* __restrict__ bias) {
    const float* Y = gbuf<YSEL>(extY);
    float* out = gbuf<OSEL>(nullptr);
    int node = (blockIdx.x * blockDim.x + threadIdx.x) >> 5;
    if (node >= N_NODES) return;
    int lane = threadIdx.x & 31;
    int hw = lane >> 4, l16 = lane & 15;
    int p0 = g_ptr[node], p1 = g_ptr[node + 1];
    if (p1 > N_EDGES) p1 = N_EDGES;
    if (p0 < 0) p0 = 0;
    float ax = 0.f, ay = 0.f, az = 0.f, aw = 0.f;
    for (int base = p0; base < p1; base += 32) {
        int idx = base + lane;
        int s = (idx < p1) ? g_srcbuf[idx] : 0;
        int m = p1 - base;
        if (m > 32) m = 32;
        for (int j = 0; j < m; j += 2) {
            int ss = __shfl_sync(0xffffffffu, s, j + hw);
            if (j + hw < m) {
                const float4* r = (const float4*)(Y + (size_t)ss * LDY);
                float4 v = r[l16];
                ax += v.x; ay += v.y; az += v.z; aw += v.w;
            }
        }
    }
    ax += __shfl_xor_sync(0xffffffffu, ax, 16);
    ay += __shfl_xor_sync(0xffffffffu, ay, 16);
    az += __shfl_xor_sync(0xffffffffu, az, 16);
    aw += __shfl_xor_sync(0xffffffffu, aw, 16);
    float inv = g_deginv[node];
    ax *= inv; ay *= inv; az *= inv; aw *= inv;
    if (COMBINE) {
        const float4* self = (const float4*)(Y + (size_t)node * LDY + 64);
        float4 sv = self[l16];
        float4 bv = ((const float4*)bias)[l16];
        ax = fmaxf(ax + bv.x + sv.x, 0.f);
        ay = fmaxf(ay + bv.y + sv.y, 0.f);
        az = fmaxf(az + bv.z + sv.z, 0.f);
        aw = fmaxf(aw + bv.w + sv.w, 0.f);
    }
    if (hw == 0) {
        float4 o; o.x = ax; o.y = ay; o.z = az; o.w = aw;
        ((float4*)(out + (size_t)node * 64))[l16] = o;
    }
}

// ---------------- GEMM: C[M,128] = act(A @ W (+bias)), pure FFMA2 inner loop ----------
// Tile 128 rows x 128 cols, 256 threads. Thread: 4 rows (2 row-pairs) x 16 cols.
// As staged COLUMN-major (row-pairs load as 64-bit lanes), Wd staged pre-DUPLICATED
// (w,w) so both FFMA2 operands come directly from LDS with zero packing movs.
#define GK 16
#define AS_S 132  // padded k-plane stride (floats): 16B-aligned, 2-way max stage conflict
template <int KT, bool ROWCAT, bool RELU, int A0SEL, int CSEL>
__global__ void __launch_bounds__(256, 2)
k_gemm(const float* __restrict__ ext0, int lda0,
       const float* __restrict__ ext1,
       const float* __restrict__ W0, const float* __restrict__ W1,
       const float* __restrict__ bias) {
    const float* A0 = gbuf<A0SEL>(ext0);
    float* C = gbuf<CSEL>(nullptr);
    __shared__ float As[GK * AS_S];                 // 8448 B, col-major As[k*AS_S + r]
    __shared__ unsigned long long Wd[GK * 128];     // 16384 B, Wd[k*128 + j] = (w,w)
    int tid = threadIdx.x;
    int row0 = blockIdx.x * 128;
    int tcol = tid >> 5;  // 0..7  -> cols tcol*16 .. +15 (warp-uniform -> B broadcast)
    int trow = tid & 31;  // 0..31 -> rows trow*4 .. +3

    unsigned long long acc[2][16];
    #pragma unroll
    for (int p = 0; p < 2; p++)
        #pragma unroll
        for (int c = 0; c < 16; c++) acc[p][c] = 0ULL;

    for (int kc = 0; kc < KT; kc += GK) {
        // stage Wd: GK x 128, duplicated
        for (int idx = tid; idx < GK * 128; idx += 256) {
            int k = idx >> 7, j = idx & 127;
            float v;
            if (ROWCAT) v = (kc + k < 64) ? W0[(kc + k) * 128 + j]
                                          : W1[(kc + k - 64) * 128 + j];
            else        v = (j < 64) ? W0[(kc + k) * 64 + j]
                                     : W1[(kc + k) * 64 + (j - 64)];
            Wd[idx] = pk2(v, v);
        }
        // stage As column-major: 128 rows x GK k
        for (int t = tid; t < 128 * (GK / 4); t += 256) {
            int r = t >> 2, q = (t & 3) * 4;
            int row = row0 + r;
            float4 v = make_float4(0.f, 0.f, 0.f, 0.f);
            if (row < N_NODES) {
                if (ROWCAT) {
                    const float* src = (kc < 64) ? (A0 + (size_t)row * 64 + kc + q)
                                                 : (ext1 + (size_t)row * 64 + kc + q - 64);
                    v = *(const float4*)src;
                } else {
                    v = *(const float4*)(A0 + (size_t)row * lda0 + kc + q);
                }
            }
            As[(q + 0) * AS_S + r] = v.x;
            As[(q + 1) * AS_S + r] = v.y;
            As[(q + 2) * AS_S + r] = v.z;
            As[(q + 3) * AS_S + r] = v.w;
        }
        __syncthreads();

        #pragma unroll
        for (int k = 0; k < GK; k++) {
            ulonglong2 av = *(const ulonglong2*)&As[k * AS_S + trow * 4];
            const ulonglong2* bp = (const ulonglong2*)&Wd[k * 128 + tcol * 16];
            ulonglong2 b0 = bp[0], b1 = bp[1], b2 = bp[2], b3 = bp[3];
            ffma2(acc[0][0], av.x, b0.x);  ffma2(acc[0][1], av.x, b0.y);
            ffma2(acc[0][2], av.x, b1.x);  ffma2(acc[0][3], av.x, b1.y);
            ffma2(acc[0][4], av.x, b2.x);  ffma2(acc[0][5], av.x, b2.y);
            ffma2(acc[0][6], av.x, b3.x);  ffma2(acc[0][7], av.x, b3.y);
            ulonglong2 b4 = bp[2 + 2], b5 = bp[2 + 3];  // cols 8..11
            ulonglong2 b6 = bp[6], b7 = bp[7];          // cols 12..15
            ffma2(acc[0][8],  av.x, b4.x); ffma2(acc[0][9],  av.x, b4.y);
            ffma2(acc[0][10], av.x, b5.x); ffma2(acc[0][11], av.x, b5.y);
            ffma2(acc[0][12], av.x, b6.x); ffma2(acc[0][13], av.x, b6.y);
            ffma2(acc[0][14], av.x, b7.x); ffma2(acc[0][15], av.x, b7.y);
            ffma2(acc[1][0], av.y, b0.x);  ffma2(acc[1][1], av.y, b0.y);
            ffma2(acc[1][2], av.y, b1.x);  ffma2(acc[1][3], av.y, b1.y);
            ffma2(acc[1][4], av.y, b2.x);  ffma2(acc[1][5], av.y, b2.y);
            ffma2(acc[1][6], av.y, b3.x);  ffma2(acc[1][7], av.y, b3.y);
            ffma2(acc[1][8],  av.y, b4.x); ffma2(acc[1][9],  av.y, b4.y);
            ffma2(acc[1][10], av.y, b5.x); ffma2(acc[1][11], av.y, b5.y);
            ffma2(acc[1][12], av.y, b6.x); ffma2(acc[1][13], av.y, b6.y);
            ffma2(acc[1][14], av.y, b7.x); ffma2(acc[1][15], av.y, b7.y);
        }
        __syncthreads();
    }

    // epilogue: 2 row-pairs x 16 cols
    int jb = tcol * 16;
    float bv[16];
    if (RELU) {
        #pragma unroll
        for (int c4 = 0; c4 < 4; c4++)
            *(float4*)&bv[c4 * 4] = *(const float4*)&bias[jb + c4 * 4];
    }
    #pragma unroll
    for (int p = 0; p < 2; p++) {
        int rbase = row0 + trow * 4 + 2 * p;
        float lo[16], hi[16];
        #pragma unroll
        for (int c = 0; c < 16; c++) upk2(acc[p][c], lo[c], hi[c]);
        #pragma unroll
        for (int h = 0; h < 2; h++) {
            int row = rbase + h;
            if (row < N_NODES) {
                float* o = h ? hi : lo;
                #pragma unroll
                for (int c4 = 0; c4 < 4; c4++) {
                    float4 v;
                    v.x = o[c4 * 4 + 0]; v.y = o[c4 * 4 + 1];
                    v.z = o[c4 * 4 + 2]; v.w = o[c4 * 4 + 3];
                    if (RELU) {
                        v.x = fmaxf(v.x + bv[c4 * 4 + 0], 0.f);
                        v.y = fmaxf(v.y + bv[c4 * 4 + 1], 0.f);
                        v.z = fmaxf(v.z + bv[c4 * 4 + 2], 0.f);
                        v.w = fmaxf(v.w + bv[c4 * 4 + 3], 0.f);
                    }
                    *(float4*)&C[(size_t)row * 128 + jb + c4 * 4] = v;
                }
            }
        }
    }
}

// ---------------- global mean pool (batch sorted -> contiguous segments) ----------------
__global__ void k_pool() {
    int g = blockIdx.x;
    int c = threadIdx.x;
    int r0 = g_gptr[g], r1 = g_gptr[g + 1];
    if (r1 > N_NODES) r1 = N_NODES;
    if (r0 < 0) r0 = 0;
    float acc = 0.f;
    for (int r = r0; r < r1; r++) acc += g_hbuf[(size_t)r * 64 + c];
    int cnt = r1 - r0;
    g_pool[g * 64 + c] = acc / (float)(cnt > 0 ? cnt : 1);
}

// ---------------- MLP head: 1024 rows, one thread per row ----------------
__global__ void k_mlp(const float* __restrict__ w1, const float* __restrict__ b1,
                      const float* __restrict__ w2, const float* __restrict__ b2,
                      const float* __restrict__ w3, const float* __restrict__ b3,
                      const float* __restrict__ w4, const float* __restrict__ b4,
                      float* __restrict__ out) {
    __shared__ float s1[64 * 64], sb1[64], s2[64 * 32], sb2[32], s3[32 * 32], sb3[32], s4[32];
    __shared__ float sb4;
    int tid = threadIdx.x;
    for (int i = tid; i < 4096; i += 256) s1[i] = w1[i];
    for (int i = tid; i < 2048; i += 256) s2[i] = w2[i];
    for (int i = tid; i < 1024; i += 256) s3[i] = w3[i];
    if (tid < 64) sb1[tid] = b1[tid];
    if (tid < 32) { sb2[tid] = b2[tid]; sb3[tid] = b3[tid]; s4[tid] = w4[tid]; }
    if (tid == 0) sb4 = b4[0];
    __syncthreads();
    int row = blockIdx.x * 256 + tid;
    if (row >= N_GRAPHS) return;
    float gin[64];
    #pragma unroll
    for (int k = 0; k < 64; k++) gin[k] = g_pool[row * 64 + k];
    float h1[64];
    for (int j = 0; j < 64; j++) {
        float a = sb1[j];
        #pragma unroll
        for (int k = 0; k < 64; k++) a += gin[k] * s1[k * 64 + j];
        h1[j] = fmaxf(a, 0.f);
    }
    float h2[32];
    for (int j = 0; j < 32; j++) {
        float a = sb2[j];
        #pragma unroll
        for (int k = 0; k < 64; k++) a += h1[k] * s2[k * 32 + j];
        h2[j] = fmaxf(a, 0.f);
    }
    float h3[32];
    for (int j = 0; j < 32; j++) {
        float a = sb3[j];
        #pragma unroll
        for (int k = 0; k < 32; k++) a += h2[k] * s3[k * 32 + j];
        h3[j] = fmaxf(a, 0.f);
    }
    float o = sb4;
    #pragma unroll
    for (int k = 0; k < 32; k++) o += h3[k] * s4[k];
    out[row] = o;
}

// ---------------- host launch: KERNEL LAUNCHES ONLY ----------------
extern "C" void kernel_launch(void* const* d_in, const int* in_sizes, int n_in,
                              void* d_out, int out_size) {
    const float* x = (const float*)d_in[0];
    const void* ei = d_in[1];
    const void* batch = d_in[2];
    const float* c1wl = (const float*)d_in[3];
    const float* c1bl = (const float*)d_in[4];
    const float* c1wr = (const float*)d_in[5];
    const float* c2wl = (const float*)d_in[6];
    const float* c2bl = (const float*)d_in[7];
    const float* c2wr = (const float*)d_in[8];
    const float* c3wl = (const float*)d_in[9];
    const float* c3bl = (const float*)d_in[10];
    const float* c3wr = (const float*)d_in[11];
    const float* c4wl = (const float*)d_in[12];
    const float* c4bl = (const float*)d_in[13];
    const float* c4wr = (const float*)d_in[14];
    const float* l1w = (const float*)d_in[15];
    const float* l1b = (const float*)d_in[16];
    const float* l2w = (const float*)d_in[17];
    const float* l2b = (const float*)d_in[18];
    const float* l3w = (const float*)d_in[19];
    const float* l3b = (const float*)d_in[20];
    const float* l4w = (const float*)d_in[21];
    const float* l4b = (const float*)d_in[22];
    float* out = (float*)d_out;

    k_zero<<<(N_NODES + 255) / 256, 256>>>((const unsigned int*)ei);
    k_cvt_count<<<(N_EDGES + 255) / 256, 256>>>(ei, batch);
    k_scanA<<<SCAN_BLOCKS, 1024>>>();
    k_scanB<<<1, 1024>>>();
    k_scanC<<<(N_NODES + 1023) / 1024, 1024>>>();
    k_fill<<<(N_EDGES + 255) / 256, 256>>>();

    int aggBlocks = (N_NODES * 32 + 255) / 256;
    int gemmBlocks = (N_NODES + 127) / 128;

    // layer 1 (aggregate-first)
    k_agg<64, false, 3, 0><<<aggBlocks, 256>>>(x, nullptr);
    k_gemm<128, true, true, 0, 1><<<gemmBlocks, 256>>>(nullptr, 64, x, c1wl, c1wr, c1bl);

    // layer 2 (transform-first)
    k_gemm<128, false, false, 1, 2><<<gemmBlocks, 256>>>(nullptr, 128, nullptr, c2wl, c2wr, nullptr);
    k_agg<128, true, 2, 1><<<aggBlocks, 256>>>(nullptr, c2bl);

    // layer 3
    k_gemm<64, false, false, 1, 2><<<gemmBlocks, 256>>>(nullptr, 64, nullptr, c3wl, c3wr, nullptr);
    k_agg<128, true, 2, 1><<<aggBlocks, 256>>>(nullptr, c3bl);

    // layer 4
    k_gemm<64, false, false, 1, 2><<<gemmBlocks, 256>>>(nullptr, 64, nullptr, c4wl, c4wr, nullptr);
    k_agg<128, true, 2, 1><<<aggBlocks, 256>>>(nullptr, c4bl);

    // pool + MLP head
    k_pool<<<N_GRAPHS, 64>>>();
    k_mlp<<<(N_GRAPHS + 255) / 256, 256>>>(l1w, l1b, l2w, l2b, l3w, l3b, l4w, l4b, out);
}

// round 9
// speedup vs baseline: 1.5913x; 1.5913x over previous
#include <cuda_runtime.h>
#include <cuda_bf16.h>
#include <cstdint>

#define N_NODES 100000
#define N_EDGES 1600000
#define N_GRAPHS 1024
#define SCAN_BLOCKS ((N_NODES + 1023) / 1024)  // 98

// ---------------- scratch (static __device__; no allocation) ----------------
__device__ int   g_is64;            // 1 if integer inputs are int64, 0 if int32
__device__ int   g_src[N_EDGES];
__device__ int   g_dst[N_EDGES];
__device__ int   g_cnt[N_NODES];
__device__ int   g_ptr[N_NODES + 1];
__device__ int   g_fill[N_NODES];
__device__ int   g_srcbuf[N_EDGES];
__device__ float g_deginv[N_NODES];
__device__ int   g_gcnt[N_GRAPHS];
__device__ int   g_gptr[N_GRAPHS + 1];
__device__ int   g_bsum[SCAN_BLOCKS];
__device__ int   g_boff[SCAN_BLOCKS];
__device__ float g_aggx[N_NODES * 64];
__device__ float g_hbuf[(size_t)N_NODES * 128];
__device__ float g_ybuf[(size_t)N_NODES * 128];
__device__ float g_pool[N_GRAPHS * 64];

// compile-time buffer selector: 0 = g_aggx, 1 = g_hbuf, 2 = g_ybuf, 3 = external
template <int SEL>
__device__ __forceinline__ float* gbuf(const float* ext) {
    if (SEL == 0) return g_aggx;
    if (SEL == 1) return g_hbuf;
    if (SEL == 2) return g_ybuf;
    return (float*)ext;
}

__device__ __forceinline__ int clampN(int v, int n) {
    return ((unsigned)v < (unsigned)n) ? v : 0;
}

// ---------------- packed f32x2 helpers ----------------
__device__ __forceinline__ unsigned long long pk2(float x, float y) {
    unsigned long long r;
    asm("mov.b64 %0, {%1, %2};" : "=l"(r) : "f"(x), "f"(y));
    return r;
}
__device__ __forceinline__ void upk2(unsigned long long v, float& x, float& y) {
    asm("mov.b64 {%0, %1}, %2;" : "=f"(x), "=f"(y) : "l"(v));
}
__device__ __forceinline__ void ffma2(unsigned long long& acc, unsigned long long a,
                                      unsigned long long b) {
    asm("fma.rn.f32x2 %0, %1, %2, %0;" : "+l"(acc) : "l"(a), "l"(b));
}

// ---------------- zero + dtype detect (fused) ----------------
__global__ void k_zero(const unsigned int* __restrict__ ei_raw) {
    int i = blockIdx.x * blockDim.x + threadIdx.x;
    if (i < N_NODES) g_cnt[i] = 0;
    if (i < N_GRAPHS) g_gcnt[i] = 0;
    if (i == 0) {
        int is64 = 1;
        for (int t = 0; t < 128; t++) {
            if (ei_raw[2 * t + 1] != 0u) { is64 = 0; break; }
        }
        g_is64 = is64;
    }
}

__global__ void k_cvt_count(const void* __restrict__ ei, const void* __restrict__ batch) {
    int i = blockIdx.x * blockDim.x + threadIdx.x;
    int is64 = g_is64;
    if (i < N_EDGES) {
        int s, d;
        if (is64) {
            s = (int)((const long long*)ei)[i];
            d = (int)((const long long*)ei)[N_EDGES + i];
        } else {
            s = ((const int*)ei)[i];
            d = ((const int*)ei)[N_EDGES + i];
        }
        s = clampN(s, N_NODES);
        d = clampN(d, N_NODES);
        g_src[i] = s;
        g_dst[i] = d;
        atomicAdd(&g_cnt[d], 1);
    }
    if (i < N_NODES) {
        int b = is64 ? (int)((const long long*)batch)[i] : ((const int*)batch)[i];
        atomicAdd(&g_gcnt[clampN(b, N_GRAPHS)], 1);
    }
}

// ---------------- parallel 3-pass scan ----------------
__global__ void k_scanA() {
    __shared__ int wsum[32];
    __shared__ int woff[32];
    int tid = threadIdx.x, lane = tid & 31, wid = tid >> 5;
    int i = blockIdx.x * 1024 + tid;
    int c = (i < N_NODES) ? g_cnt[i] : 0;
    int incl = c;
    #pragma unroll
    for (int o = 1; o < 32; o <<= 1) {
        int v = __shfl_up_sync(0xffffffffu, incl, o);
        if (lane >= o) incl += v;
    }
    if (lane == 31) wsum[wid] = incl;
    __syncthreads();
    if (wid == 0) {
        int v = wsum[lane];
        int s = v;
        #pragma unroll
        for (int o = 1; o < 32; o <<= 1) {
            int t = __shfl_up_sync(0xffffffffu, s, o);
            if (lane >= o) s += t;
        }
        woff[lane] = s - v;
        if (lane == 31) wsum[0] = s;
    }
    __syncthreads();
    int excl = woff[wid] + (incl - c);
    if (i < N_NODES) g_ptr[i] = excl;
    if (tid == 0) g_bsum[blockIdx.x] = wsum[0];
}

__global__ void k_scanB() {
    __shared__ int wsum[32];
    int tid = threadIdx.x, lane = tid & 31, wid = tid >> 5;
    if (wid == 0) {
        int carry = 0;
        for (int base = 0; base < SCAN_BLOCKS; base += 32) {
            int idx = base + lane;
            int v = (idx < SCAN_BLOCKS) ? g_bsum[idx] : 0;
            int s = v;
            #pragma unroll
            for (int o = 1; o < 32; o <<= 1) {
                int t = __shfl_up_sync(0xffffffffu, s, o);
                if (lane >= o) s += t;
            }
            if (idx < SCAN_BLOCKS) g_boff[idx] = carry + s - v;
            carry += __shfl_sync(0xffffffffu, s, 31);
        }
        if (lane == 0) g_ptr[N_NODES] = carry;
    }
    __syncthreads();
    {
        int c = g_gcnt[tid];
        int incl = c;
        #pragma unroll
        for (int o = 1; o < 32; o <<= 1) {
            int v = __shfl_up_sync(0xffffffffu, incl, o);
            if (lane >= o) incl += v;
        }
        if (lane == 31) wsum[wid] = incl;
        __syncthreads();
        if (wid == 0) {
            int v = wsum[lane];
            int s = v;
            #pragma unroll
            for (int o = 1; o < 32; o <<= 1) {
                int t = __shfl_up_sync(0xffffffffu, s, o);
                if (lane >= o) s += t;
            }
            wsum[lane] = s - v;
        }
        __syncthreads();
        int excl = wsum[wid] + (incl - c);
        g_gptr[tid] = excl;
        if (tid == 1023) g_gptr[N_GRAPHS] = excl + c;
    }
}

__global__ void k_scanC() {
    int i = blockIdx.x * blockDim.x + threadIdx.x;
    if (i < N_NODES) {
        int p = g_ptr[i] + g_boff[i >> 10];
        g_ptr[i] = p;
        g_fill[i] = p;
        int c = g_cnt[i];
        g_deginv[i] = 1.0f / (float)(c > 0 ? c : 1);
    }
}

__global__ void k_fill() {
    int e = blockIdx.x * blockDim.x + threadIdx.x;
    if (e < N_EDGES) {
        int p = atomicAdd(&g_fill[g_dst[e]], 1);
        g_srcbuf[clampN(p, N_EDGES)] = g_src[e];
    }
}

// ---------------- aggregation: warp/node, half-warp/edge, depth-2 SW pipeline ----------
// COMBINE=false: out[n,0:64] = mean_{src in N(n)} Y[src,0:64]
// COMBINE=true : out[n,0:64] = relu(mean Y[src,0:64] + bias + Y[n,64:128])
// Accumulation order identical to the non-pipelined version (ascending edge index),
// so numerics are bit-identical; only load issue order changes (MLP 1 -> ~3).
template <int LDY, bool COMBINE, int YSEL, int OSEL>
__global__ void k_agg(const float* __restrict__ extY, const float* __restrict__ bias) {
    const float* Y = gbuf<YSEL>(extY);
    float* out = gbuf<OSEL>(nullptr);
    int node = (blockIdx.x * blockDim.x + threadIdx.x) >> 5;
    if (node >= N_NODES) return;
    int lane = threadIdx.x & 31;
    int hw = lane >> 4, l16 = lane & 15;
    int p0 = g_ptr[node], p1 = g_ptr[node + 1];
    if (p1 > N_EDGES) p1 = N_EDGES;
    if (p0 < 0) p0 = 0;
    float ax = 0.f, ay = 0.f, az = 0.f, aw = 0.f;
    const float4 Z = make_float4(0.f, 0.f, 0.f, 0.f);
    for (int base = p0; base < p1; base += 32) {
        int idx = base + lane;
        int s = (idx < p1) ? g_srcbuf[idx] : 0;
        int m = p1 - base;
        if (m > 32) m = 32;
        // prime pipeline: edges hw and hw+2 for this half-warp
        int ss0 = __shfl_sync(0xffffffffu, s, hw);
        int ss1 = __shfl_sync(0xffffffffu, s, (2 + hw) & 31);
        float4 v0 = Z, v1 = Z;
        if (hw < m)     v0 = ((const float4*)(Y + (size_t)ss0 * LDY))[l16];
        if (2 + hw < m) v1 = ((const float4*)(Y + (size_t)ss1 * LDY))[l16];
        for (int jj = 0; jj < m; jj += 2) {
            int ssn = __shfl_sync(0xffffffffu, s, (jj + 4 + hw) & 31);
            float4 vn = Z;
            if (jj + 4 + hw < m)
                vn = ((const float4*)(Y + (size_t)ssn * LDY))[l16];
            ax += v0.x; ay += v0.y; az += v0.z; aw += v0.w;
            v0 = v1; v1 = vn;
        }
    }
    ax += __shfl_xor_sync(0xffffffffu, ax, 16);
    ay += __shfl_xor_sync(0xffffffffu, ay, 16);
    az += __shfl_xor_sync(0xffffffffu, az, 16);
    aw += __shfl_xor_sync(0xffffffffu, aw, 16);
    float inv = g_deginv[node];
    ax *= inv; ay *= inv; az *= inv; aw *= inv;
    if (COMBINE) {
        const float4* self = (const float4*)(Y + (size_t)node * LDY + 64);
        float4 sv = self[l16];
        float4 bv = ((const float4*)bias)[l16];
        ax = fmaxf(ax + bv.x + sv.x, 0.f);
        ay = fmaxf(ay + bv.y + sv.y, 0.f);
        az = fmaxf(az + bv.z + sv.z, 0.f);
        aw = fmaxf(aw + bv.w + sv.w, 0.f);
    }
    if (hw == 0) {
        float4 o; o.x = ax; o.y = ay; o.z = az; o.w = aw;
        ((float4*)(out + (size_t)node * 64))[l16] = o;
    }
}

// ---------------- GEMM (reverted to proven R7 version): FFMA2 with packing movs ------
#define AS_LD 36  // padded k-stride (floats) for bank-conflict-free staging
template <int KT, bool ROWCAT, bool RELU, int A0SEL, int CSEL>
__global__ void __launch_bounds__(256, 2)
k_gemm(const float* __restrict__ ext0, int lda0,
       const float* __restrict__ ext1,
       const float* __restrict__ W0, const float* __restrict__ W1,
       const float* __restrict__ bias) {
    const float* A0 = gbuf<A0SEL>(ext0);
    float* C = gbuf<CSEL>(nullptr);
    __shared__ float Ws[32 * 128];     // 16 KB
    __shared__ float As[128 * AS_LD];  // 18 KB
    int tid = threadIdx.x;
    int row0 = blockIdx.x * 128;
    int trow = tid >> 4;  // 0..15, 8 rows each
    int tcol = tid & 15;  // 0..15, 8 cols each

    unsigned long long acc[8][4];
    #pragma unroll
    for (int i = 0; i < 8; i++)
        #pragma unroll
        for (int p = 0; p < 4; p++) acc[i][p] = 0ULL;

    for (int kc = 0; kc < KT; kc += 32) {
        for (int idx = tid; idx < 32 * 128; idx += 256) {
            int k = idx >> 7, j = idx & 127;
            float v;
            if (ROWCAT) v = (kc + k < 64) ? W0[(kc + k) * 128 + j]
                                          : W1[(kc + k - 64) * 128 + j];
            else        v = (j < 64) ? W0[(kc + k) * 64 + j]
                                     : W1[(kc + k) * 64 + (j - 64)];
            Ws[idx] = v;
        }
        for (int t = tid; t < 128 * 8; t += 256) {
            int r = t >> 3, q = (t & 7) * 4;
            int row = row0 + r;
            float4 v = make_float4(0.f, 0.f, 0.f, 0.f);
            if (row < N_NODES) {
                if (ROWCAT) {
                    const float* src = (kc < 64) ? (A0 + (size_t)row * 64 + kc + q)
                                                 : (ext1 + (size_t)row * 64 + kc + q - 64);
                    v = *(const float4*)src;
                } else {
                    v = *(const float4*)(A0 + (size_t)row * lda0 + kc + q);
                }
            }
            *(float4*)&As[r * AS_LD + q] = v;
        }
        __syncthreads();

        #pragma unroll
        for (int k = 0; k < 32; k += 2) {
            float4 b0a = *(const float4*)&Ws[k * 128 + tcol * 8];
            float4 b0b = *(const float4*)&Ws[k * 128 + tcol * 8 + 4];
            float4 b1a = *(const float4*)&Ws[(k + 1) * 128 + tcol * 8];
            float4 b1b = *(const float4*)&Ws[(k + 1) * 128 + tcol * 8 + 4];
            unsigned long long B0[4], B1[4];
            B0[0] = pk2(b0a.x, b0a.y); B0[1] = pk2(b0a.z, b0a.w);
            B0[2] = pk2(b0b.x, b0b.y); B0[3] = pk2(b0b.z, b0b.w);
            B1[0] = pk2(b1a.x, b1a.y); B1[1] = pk2(b1a.z, b1a.w);
            B1[2] = pk2(b1b.x, b1b.y); B1[3] = pk2(b1b.z, b1b.w);
            #pragma unroll
            for (int i = 0; i < 8; i++) {
                float2 a = *(const float2*)&As[(trow * 8 + i) * AS_LD + k];
                unsigned long long a0 = pk2(a.x, a.x);
                unsigned long long a1 = pk2(a.y, a.y);
                ffma2(acc[i][0], a0, B0[0]);
                ffma2(acc[i][1], a0, B0[1]);
                ffma2(acc[i][2], a0, B0[2]);
                ffma2(acc[i][3], a0, B0[3]);
                ffma2(acc[i][0], a1, B1[0]);
                ffma2(acc[i][1], a1, B1[1]);
                ffma2(acc[i][2], a1, B1[2]);
                ffma2(acc[i][3], a1, B1[3]);
            }
        }
        __syncthreads();
    }

    int jbase = tcol * 8;
    float4 bv0, bv1;
    if (RELU) {
        bv0 = *(const float4*)&bias[jbase];
        bv1 = *(const float4*)&bias[jbase + 4];
    }
    #pragma unroll
    for (int i = 0; i < 8; i++) {
        int row = row0 + trow * 8 + i;
        if (row < N_NODES) {
            float4 o0, o1;
            upk2(acc[i][0], o0.x, o0.y);
            upk2(acc[i][1], o0.z, o0.w);
            upk2(acc[i][2], o1.x, o1.y);
            upk2(acc[i][3], o1.z, o1.w);
            if (RELU) {
                o0.x = fmaxf(o0.x + bv0.x, 0.f); o0.y = fmaxf(o0.y + bv0.y, 0.f);
                o0.z = fmaxf(o0.z + bv0.z, 0.f); o0.w = fmaxf(o0.w + bv0.w, 0.f);
                o1.x = fmaxf(o1.x + bv1.x, 0.f); o1.y = fmaxf(o1.y + bv1.y, 0.f);
                o1.z = fmaxf(o1.z + bv1.z, 0.f); o1.w = fmaxf(o1.w + bv1.w, 0.f);
            }
            *(float4*)&C[(size_t)row * 128 + jbase] = o0;
            *(float4*)&C[(size_t)row * 128 + jbase + 4] = o1;
        }
    }
}

// ---------------- global mean pool (batch sorted -> contiguous segments) ----------------
__global__ void k_pool() {
    int g = blockIdx.x;
    int c = threadIdx.x;
    int r0 = g_gptr[g], r1 = g_gptr[g + 1];
    if (r1 > N_NODES) r1 = N_NODES;
    if (r0 < 0) r0 = 0;
    float acc = 0.f;
    for (int r = r0; r < r1; r++) acc += g_hbuf[(size_t)r * 64 + c];
    int cnt = r1 - r0;
    g_pool[g * 64 + c] = acc / (float)(cnt > 0 ? cnt : 1);
}

// ---------------- MLP head: 1024 rows, one thread per row ----------------
__global__ void k_mlp(const float* __restrict__ w1, const float* __restrict__ b1,
                      const float* __restrict__ w2, const float* __restrict__ b2,
                      const float* __restrict__ w3, const float* __restrict__ b3,
                      const float* __restrict__ w4, const float* __restrict__ b4,
                      float* __restrict__ out) {
    __shared__ float s1[64 * 64], sb1[64], s2[64 * 32], sb2[32], s3[32 * 32], sb3[32], s4[32];
    __shared__ float sb4;
    int tid = threadIdx.x;
    for (int i = tid; i < 4096; i += 256) s1[i] = w1[i];
    for (int i = tid; i < 2048; i += 256) s2[i] = w2[i];
    for (int i = tid; i < 1024; i += 256) s3[i] = w3[i];
    if (tid < 64) sb1[tid] = b1[tid];
    if (tid < 32) { sb2[tid] = b2[tid]; sb3[tid] = b3[tid]; s4[tid] = w4[tid]; }
    if (tid == 0) sb4 = b4[0];
    __syncthreads();
    int row = blockIdx.x * 256 + tid;
    if (row >= N_GRAPHS) return;
    float gin[64];
    #pragma unroll
    for (int k = 0; k < 64; k++) gin[k] = g_pool[row * 64 + k];
    float h1[64];
    for (int j = 0; j < 64; j++) {
        float a = sb1[j];
        #pragma unroll
        for (int k = 0; k < 64; k++) a += gin[k] * s1[k * 64 + j];
        h1[j] = fmaxf(a, 0.f);
    }
    float h2[32];
    for (int j = 0; j < 32; j++) {
        float a = sb2[j];
        #pragma unroll
        for (int k = 0; k < 64; k++) a += h1[k] * s2[k * 32 + j];
        h2[j] = fmaxf(a, 0.f);
    }
    float h3[32];
    for (int j = 0; j < 32; j++) {
        float a = sb3[j];
        #pragma unroll
        for (int k = 0; k < 32; k++) a += h2[k] * s3[k * 32 + j];
        h3[j] = fmaxf(a, 0.f);
    }
    float o = sb4;
    #pragma unroll
    for (int k = 0; k < 32; k++) o += h3[k] * s4[k];
    out[row] = o;
}

// ---------------- host launch: KERNEL LAUNCHES ONLY ----------------
extern "C" void kernel_launch(void* const* d_in, const int* in_sizes, int n_in,
                              void* d_out, int out_size) {
    const float* x = (const float*)d_in[0];
    const void* ei = d_in[1];
    const void* batch = d_in[2];
    const float* c1wl = (const float*)d_in[3];
    const float* c1bl = (const float*)d_in[4];
    const float* c1wr = (const float*)d_in[5];
    const float* c2wl = (const float*)d_in[6];
    const float* c2bl = (const float*)d_in[7];
    const float* c2wr = (const float*)d_in[8];
    const float* c3wl = (const float*)d_in[9];
    const float* c3bl = (const float*)d_in[10];
    const float* c3wr = (const float*)d_in[11];
    const float* c4wl = (const float*)d_in[12];
    const float* c4bl = (const float*)d_in[13];
    const float* c4wr = (const float*)d_in[14];
    const float* l1w = (const float*)d_in[15];
    const float* l1b = (const float*)d_in[16];
    const float* l2w = (const float*)d_in[17];
    const float* l2b = (const float*)d_in[18];
    const float* l3w = (const float*)d_in[19];
    const float* l3b = (const float*)d_in[20];
    const float* l4w = (const float*)d_in[21];
    const float* l4b = (const float*)d_in[22];
    float* out = (float*)d_out;

    k_zero<<<(N_NODES + 255) / 256, 256>>>((const unsigned int*)ei);
    k_cvt_count<<<(N_EDGES + 255) / 256, 256>>>(ei, batch);
    k_scanA<<<SCAN_BLOCKS, 1024>>>();
    k_scanB<<<1, 1024>>>();
    k_scanC<<<(N_NODES + 1023) / 1024, 1024>>>();
    k_fill<<<(N_EDGES + 255) / 256, 256>>>();

    int aggBlocks = (N_NODES * 32 + 255) / 256;
    int gemmBlocks = (N_NODES + 127) / 128;

    // layer 1 (aggregate-first)
    k_agg<64, false, 3, 0><<<aggBlocks, 256>>>(x, nullptr);
    k_gemm<128, true, true, 0, 1><<<gemmBlocks, 256>>>(nullptr, 64, x, c1wl, c1wr, c1bl);

    // layer 2 (transform-first)
    k_gemm<128, false, false, 1, 2><<<gemmBlocks, 256>>>(nullptr, 128, nullptr, c2wl, c2wr, nullptr);
    k_agg<128, true, 2, 1><<<aggBlocks, 256>>>(nullptr, c2bl);

    // layer 3
    k_gemm<64, false, false, 1, 2><<<gemmBlocks, 256>>>(nullptr, 64, nullptr, c3wl, c3wr, nullptr);
    k_agg<128, true, 2, 1><<<aggBlocks, 256>>>(nullptr, c3bl);

    // layer 4
    k_gemm<64, false, false, 1, 2><<<gemmBlocks, 256>>>(nullptr, 64, nullptr, c4wl, c4wr, nullptr);
    k_agg<128, true, 2, 1><<<aggBlocks, 256>>>(nullptr, c4bl);

    // pool + MLP head
    k_pool<<<N_GRAPHS, 64>>>();
    k_mlp<<<(N_GRAPHS + 255) / 256, 256>>>(l1w, l1b, l2w, l2b, l3w, l3b, l4w, l4b, out);
}

// round 10
// speedup vs baseline: 1.6667x; 1.0474x over previous
#include <cuda_runtime.h>
#include <cuda_bf16.h>
#include <cuda_fp16.h>
#include <cstdint>

#define N_NODES 100000
#define N_EDGES 1600000
#define N_GRAPHS 1024
#define SCAN_BLOCKS ((N_NODES + 1023) / 1024)  // 98

// ---------------- scratch (static __device__; no allocation) ----------------
__device__ int    g_is64;
__device__ int    g_src[N_EDGES];
__device__ int    g_dst[N_EDGES];
__device__ int    g_cnt[N_NODES];
__device__ int    g_ptr[N_NODES + 1];
__device__ int    g_fill[N_NODES];
__device__ int    g_srcbuf[N_EDGES];
__device__ float  g_deginv[N_NODES];
__device__ int    g_gcnt[N_GRAPHS];
__device__ int    g_gptr[N_GRAPHS + 1];
__device__ int    g_bsum[SCAN_BLOCKS];
__device__ int    g_boff[SCAN_BLOCKS];
__device__ float  g_aggx[N_NODES * 64];
__device__ float  g_hbuf[(size_t)N_NODES * 128];
__device__ __half g_xh[(size_t)N_NODES * 64];   // fp16 copy of x (layer-1 gather)
__device__ __half g_yh[(size_t)N_NODES * 64];   // fp16 gather half of y (layers 2-4)
__device__ float  g_ys[(size_t)N_NODES * 64];   // fp32 self half of y (layers 2-4)
__device__ float  g_pool[N_GRAPHS * 64];

// compile-time buffer selector: 0 = g_aggx, 1 = g_hbuf, 3 = external
template <int SEL>
__device__ __forceinline__ float* gbuf(const float* ext) {
    if (SEL == 0) return g_aggx;
    if (SEL == 1) return g_hbuf;
    return (float*)ext;
}

__device__ __forceinline__ int clampN(int v, int n) {
    return ((unsigned)v < (unsigned)n) ? v : 0;
}

// ---------------- packed f32x2 helpers ----------------
__device__ __forceinline__ unsigned long long pk2(float x, float y) {
    unsigned long long r;
    asm("mov.b64 %0, {%1, %2};" : "=l"(r) : "f"(x), "f"(y));
    return r;
}
__device__ __forceinline__ void upk2(unsigned long long v, float& x, float& y) {
    asm("mov.b64 {%0, %1}, %2;" : "=f"(x), "=f"(y) : "l"(v));
}
__device__ __forceinline__ void ffma2(unsigned long long& acc, unsigned long long a,
                                      unsigned long long b) {
    asm("fma.rn.f32x2 %0, %1, %2, %0;" : "+l"(acc) : "l"(a), "l"(b));
}

// ---------------- zero + dtype detect (fused) ----------------
__global__ void k_zero(const unsigned int* __restrict__ ei_raw) {
    int i = blockIdx.x * blockDim.x + threadIdx.x;
    if (i < N_NODES) g_cnt[i] = 0;
    if (i < N_GRAPHS) g_gcnt[i] = 0;
    if (i == 0) {
        int is64 = 1;
        for (int t = 0; t < 128; t++) {
            if (ei_raw[2 * t + 1] != 0u) { is64 = 0; break; }
        }
        g_is64 = is64;
    }
}

__global__ void k_cvt_count(const void* __restrict__ ei, const void* __restrict__ batch) {
    int i = blockIdx.x * blockDim.x + threadIdx.x;
    int is64 = g_is64;
    if (i < N_EDGES) {
        int s, d;
        if (is64) {
            s = (int)((const long long*)ei)[i];
            d = (int)((const long long*)ei)[N_EDGES + i];
        } else {
            s = ((const int*)ei)[i];
            d = ((const int*)ei)[N_EDGES + i];
        }
        s = clampN(s, N_NODES);
        d = clampN(d, N_NODES);
        g_src[i] = s;
        g_dst[i] = d;
        atomicAdd(&g_cnt[d], 1);
    }
    if (i < N_NODES) {
        int b = is64 ? (int)((const long long*)batch)[i] : ((const int*)batch)[i];
        atomicAdd(&g_gcnt[clampN(b, N_GRAPHS)], 1);
    }
}

// ---------------- x -> fp16 (once; layer-1 gather source) ----------------
__global__ void k_x2h(const float* __restrict__ x) {
    int i = blockIdx.x * blockDim.x + threadIdx.x;  // one thread per 4 floats
    if (i < N_NODES * 16) {
        float4 v = ((const float4*)x)[i];
        __half2 a = __floats2half2_rn(v.x, v.y);
        __half2 b = __floats2half2_rn(v.z, v.w);
        uint2 u;
        u.x = *(unsigned*)&a;
        u.y = *(unsigned*)&b;
        ((uint2*)g_xh)[i] = u;
    }
}

// ---------------- parallel 3-pass scan ----------------
__global__ void k_scanA() {
    __shared__ int wsum[32];
    __shared__ int woff[32];
    int tid = threadIdx.x, lane = tid & 31, wid = tid >> 5;
    int i = blockIdx.x * 1024 + tid;
    int c = (i < N_NODES) ? g_cnt[i] : 0;
    int incl = c;
    #pragma unroll
    for (int o = 1; o < 32; o <<= 1) {
        int v = __shfl_up_sync(0xffffffffu, incl, o);
        if (lane >= o) incl += v;
    }
    if (lane == 31) wsum[wid] = incl;
    __syncthreads();
    if (wid == 0) {
        int v = wsum[lane];
        int s = v;
        #pragma unroll
        for (int o = 1; o < 32; o <<= 1) {
            int t = __shfl_up_sync(0xffffffffu, s, o);
            if (lane >= o) s += t;
        }
        woff[lane] = s - v;
        if (lane == 31) wsum[0] = s;
    }
    __syncthreads();
    int excl = woff[wid] + (incl - c);
    if (i < N_NODES) g_ptr[i] = excl;
    if (tid == 0) g_bsum[blockIdx.x] = wsum[0];
}

__global__ void k_scanB() {
    __shared__ int wsum[32];
    int tid = threadIdx.x, lane = tid & 31, wid = tid >> 5;
    if (wid == 0) {
        int carry = 0;
        for (int base = 0; base < SCAN_BLOCKS; base += 32) {
            int idx = base + lane;
            int v = (idx < SCAN_BLOCKS) ? g_bsum[idx] : 0;
            int s = v;
            #pragma unroll
            for (int o = 1; o < 32; o <<= 1) {
                int t = __shfl_up_sync(0xffffffffu, s, o);
                if (lane >= o) s += t;
            }
            if (idx < SCAN_BLOCKS) g_boff[idx] = carry + s - v;
            carry += __shfl_sync(0xffffffffu, s, 31);
        }
        if (lane == 0) g_ptr[N_NODES] = carry;
    }
    __syncthreads();
    {
        int c = g_gcnt[tid];
        int incl = c;
        #pragma unroll
        for (int o = 1; o < 32; o <<= 1) {
            int v = __shfl_up_sync(0xffffffffu, incl, o);
            if (lane >= o) incl += v;
        }
        if (lane == 31) wsum[wid] = incl;
        __syncthreads();
        if (wid == 0) {
            int v = wsum[lane];
            int s = v;
            #pragma unroll
            for (int o = 1; o < 32; o <<= 1) {
                int t = __shfl_up_sync(0xffffffffu, s, o);
                if (lane >= o) s += t;
            }
            wsum[lane] = s - v;
        }
        __syncthreads();
        int excl = wsum[wid] + (incl - c);
        g_gptr[tid] = excl;
        if (tid == 1023) g_gptr[N_GRAPHS] = excl + c;
    }
}

__global__ void k_scanC() {
    int i = blockIdx.x * blockDim.x + threadIdx.x;
    if (i < N_NODES) {
        int p = g_ptr[i] + g_boff[i >> 10];
        g_ptr[i] = p;
        g_fill[i] = p;
        int c = g_cnt[i];
        g_deginv[i] = 1.0f / (float)(c > 0 ? c : 1);
    }
}

__global__ void k_fill() {
    int e = blockIdx.x * blockDim.x + threadIdx.x;
    if (e < N_EDGES) {
        int p = atomicAdd(&g_fill[g_dst[e]], 1);
        g_srcbuf[clampN(p, N_EDGES)] = g_src[e];
    }
}

// ---------------- aggregation (fp16 gather): warp/node, half-warp/edge ----------------
// COMBINE=false: out[n,0:64] = mean_{src} g_xh[src,0:64]            -> g_aggx
// COMBINE=true : out[n,0:64] = relu(mean g_yh[src,0:64] + bias + g_ys[n,0:64]) -> g_hbuf
// Each lane loads 4 halves (8 B); half-warp covers a 128 B row in one wavefront.
template <bool COMBINE, int OSEL>
__global__ void k_aggh(const float* __restrict__ bias) {
    const __half* Yh = COMBINE ? g_yh : g_xh;
    float* out = gbuf<OSEL>(nullptr);
    int node = (blockIdx.x * blockDim.x + threadIdx.x) >> 5;
    if (node >= N_NODES) return;
    int lane = threadIdx.x & 31;
    int hw = lane >> 4, l16 = lane & 15;
    int p0 = g_ptr[node], p1 = g_ptr[node + 1];
    if (p1 > N_EDGES) p1 = N_EDGES;
    if (p0 < 0) p0 = 0;
    float ax = 0.f, ay = 0.f, az = 0.f, aw = 0.f;
    for (int base = p0; base < p1; base += 32) {
        int idx = base + lane;
        int s = (idx < p1) ? g_srcbuf[idx] : 0;
        int m = p1 - base;
        if (m > 32) m = 32;
        for (int j = 0; j < m; j += 2) {
            int ss = __shfl_sync(0xffffffffu, s, j + hw);
            if (j + hw < m) {
                uint2 u = *(const uint2*)(Yh + (size_t)ss * 64 + l16 * 4);
                float2 f0 = __half22float2(*(const __half2*)&u.x);
                float2 f1 = __half22float2(*(const __half2*)&u.y);
                ax += f0.x; ay += f0.y; az += f1.x; aw += f1.y;
            }
        }
    }
    ax += __shfl_xor_sync(0xffffffffu, ax, 16);
    ay += __shfl_xor_sync(0xffffffffu, ay, 16);
    az += __shfl_xor_sync(0xffffffffu, az, 16);
    aw += __shfl_xor_sync(0xffffffffu, aw, 16);
    float inv = g_deginv[node];
    ax *= inv; ay *= inv; az *= inv; aw *= inv;
    if (COMBINE) {
        float4 sv = ((const float4*)(g_ys + (size_t)node * 64))[l16];
        float4 bv = ((const float4*)bias)[l16];
        ax = fmaxf(ax + bv.x + sv.x, 0.f);
        ay = fmaxf(ay + bv.y + sv.y, 0.f);
        az = fmaxf(az + bv.z + sv.z, 0.f);
        aw = fmaxf(aw + bv.w + sv.w, 0.f);
    }
    if (hw == 0) {
        float4 o; o.x = ax; o.y = ay; o.z = az; o.w = aw;
        ((float4*)(out + (size_t)node * 64))[l16] = o;
    }
}

// ---------------- GEMM (R7 mainloop). SPLIT epilogue: cols 0:64 -> fp16 g_yh,
// cols 64:128 -> fp32 g_ys. Non-split: fp32 C buffer (CSEL) with optional relu+bias.
#define AS_LD 36
template <int KT, bool ROWCAT, bool RELU, int A0SEL, int CSEL, bool SPLIT>
__global__ void __launch_bounds__(256, 2)
k_gemm(const float* __restrict__ ext0, int lda0,
       const float* __restrict__ ext1,
       const float* __restrict__ W0, const float* __restrict__ W1,
       const float* __restrict__ bias) {
    const float* A0 = gbuf<A0SEL>(ext0);
    float* C = gbuf<CSEL>(nullptr);
    __shared__ float Ws[32 * 128];
    __shared__ float As[128 * AS_LD];
    int tid = threadIdx.x;
    int row0 = blockIdx.x * 128;
    int trow = tid >> 4;
    int tcol = tid & 15;

    unsigned long long acc[8][4];
    #pragma unroll
    for (int i = 0; i < 8; i++)
        #pragma unroll
        for (int p = 0; p < 4; p++) acc[i][p] = 0ULL;

    for (int kc = 0; kc < KT; kc += 32) {
        for (int idx = tid; idx < 32 * 128; idx += 256) {
            int k = idx >> 7, j = idx & 127;
            float v;
            if (ROWCAT) v = (kc + k < 64) ? W0[(kc + k) * 128 + j]
                                          : W1[(kc + k - 64) * 128 + j];
            else        v = (j < 64) ? W0[(kc + k) * 64 + j]
                                     : W1[(kc + k) * 64 + (j - 64)];
            Ws[idx] = v;
        }
        for (int t = tid; t < 128 * 8; t += 256) {
            int r = t >> 3, q = (t & 7) * 4;
            int row = row0 + r;
            float4 v = make_float4(0.f, 0.f, 0.f, 0.f);
            if (row < N_NODES) {
                if (ROWCAT) {
                    const float* src = (kc < 64) ? (A0 + (size_t)row * 64 + kc + q)
                                                 : (ext1 + (size_t)row * 64 + kc + q - 64);
                    v = *(const float4*)src;
                } else {
                    v = *(const float4*)(A0 + (size_t)row * lda0 + kc + q);
                }
            }
            *(float4*)&As[r * AS_LD + q] = v;
        }
        __syncthreads();

        #pragma unroll
        for (int k = 0; k < 32; k += 2) {
            float4 b0a = *(const float4*)&Ws[k * 128 + tcol * 8];
            float4 b0b = *(const float4*)&Ws[k * 128 + tcol * 8 + 4];
            float4 b1a = *(const float4*)&Ws[(k + 1) * 128 + tcol * 8];
            float4 b1b = *(const float4*)&Ws[(k + 1) * 128 + tcol * 8 + 4];
            unsigned long long B0[4], B1[4];
            B0[0] = pk2(b0a.x, b0a.y); B0[1] = pk2(b0a.z, b0a.w);
            B0[2] = pk2(b0b.x, b0b.y); B0[3] = pk2(b0b.z, b0b.w);
            B1[0] = pk2(b1a.x, b1a.y); B1[1] = pk2(b1a.z, b1a.w);
            B1[2] = pk2(b1b.x, b1b.y); B1[3] = pk2(b1b.z, b1b.w);
            #pragma unroll
            for (int i = 0; i < 8; i++) {
                float2 a = *(const float2*)&As[(trow * 8 + i) * AS_LD + k];
                unsigned long long a0 = pk2(a.x, a.x);
                unsigned long long a1 = pk2(a.y, a.y);
                ffma2(acc[i][0], a0, B0[0]);
                ffma2(acc[i][1], a0, B0[1]);
                ffma2(acc[i][2], a0, B0[2]);
                ffma2(acc[i][3], a0, B0[3]);
                ffma2(acc[i][0], a1, B1[0]);
                ffma2(acc[i][1], a1, B1[1]);
                ffma2(acc[i][2], a1, B1[2]);
                ffma2(acc[i][3], a1, B1[3]);
            }
        }
        __syncthreads();
    }

    int jbase = tcol * 8;
    float4 bv0, bv1;
    if (RELU) {
        bv0 = *(const float4*)&bias[jbase];
        bv1 = *(const float4*)&bias[jbase + 4];
    }
    #pragma unroll
    for (int i = 0; i < 8; i++) {
        int row = row0 + trow * 8 + i;
        if (row < N_NODES) {
            float4 o0, o1;
            upk2(acc[i][0], o0.x, o0.y);
            upk2(acc[i][1], o0.z, o0.w);
            upk2(acc[i][2], o1.x, o1.y);
            upk2(acc[i][3], o1.z, o1.w);
            if (RELU) {
                o0.x = fmaxf(o0.x + bv0.x, 0.f); o0.y = fmaxf(o0.y + bv0.y, 0.f);
                o0.z = fmaxf(o0.z + bv0.z, 0.f); o0.w = fmaxf(o0.w + bv0.w, 0.f);
                o1.x = fmaxf(o1.x + bv1.x, 0.f); o1.y = fmaxf(o1.y + bv1.y, 0.f);
                o1.z = fmaxf(o1.z + bv1.z, 0.f); o1.w = fmaxf(o1.w + bv1.w, 0.f);
            }
            if (SPLIT) {
                if (jbase < 64) {
                    __half2 p0 = __floats2half2_rn(o0.x, o0.y);
                    __half2 p1 = __floats2half2_rn(o0.z, o0.w);
                    __half2 p2 = __floats2half2_rn(o1.x, o1.y);
                    __half2 p3 = __floats2half2_rn(o1.z, o1.w);
                    uint4 u;
                    u.x = *(unsigned*)&p0; u.y = *(unsigned*)&p1;
                    u.z = *(unsigned*)&p2; u.w = *(unsigned*)&p3;
                    *(uint4*)(g_yh + (size_t)row * 64 + jbase) = u;
                } else {
                    *(float4*)&g_ys[(size_t)row * 64 + jbase - 64] = o0;
                    *(float4*)&g_ys[(size_t)row * 64 + jbase - 60] = o1;
                }
            } else {
                *(float4*)&C[(size_t)row * 128 + jbase] = o0;
                *(float4*)&C[(size_t)row * 128 + jbase + 4] = o1;
            }
        }
    }
}

// ---------------- global mean pool (batch sorted -> contiguous segments) ----------------
__global__ void k_pool() {
    int g = blockIdx.x;
    int c = threadIdx.x;
    int r0 = g_gptr[g], r1 = g_gptr[g + 1];
    if (r1 > N_NODES) r1 = N_NODES;
    if (r0 < 0) r0 = 0;
    float acc = 0.f;
    for (int r = r0; r < r1; r++) acc += g_hbuf[(size_t)r * 64 + c];
    int cnt = r1 - r0;
    g_pool[g * 64 + c] = acc / (float)(cnt > 0 ? cnt : 1);
}

// ---------------- MLP head: 1024 rows, one thread per row ----------------
__global__ void k_mlp(const float* __restrict__ w1, const float* __restrict__ b1,
                      const float* __restrict__ w2, const float* __restrict__ b2,
                      const float* __restrict__ w3, const float* __restrict__ b3,
                      const float* __restrict__ w4, const float* __restrict__ b4,
                      float* __restrict__ out) {
    __shared__ float s1[64 * 64], sb1[64], s2[64 * 32], sb2[32], s3[32 * 32], sb3[32], s4[32];
    __shared__ float sb4;
    int tid = threadIdx.x;
    for (int i = tid; i < 4096; i += 256) s1[i] = w1[i];
    for (int i = tid; i < 2048; i += 256) s2[i] = w2[i];
    for (int i = tid; i < 1024; i += 256) s3[i] = w3[i];
    if (tid < 64) sb1[tid] = b1[tid];
    if (tid < 32) { sb2[tid] = b2[tid]; sb3[tid] = b3[tid]; s4[tid] = w4[tid]; }
    if (tid == 0) sb4 = b4[0];
    __syncthreads();
    int row = blockIdx.x * 256 + tid;
    if (row >= N_GRAPHS) return;
    float gin[64];
    #pragma unroll
    for (int k = 0; k < 64; k++) gin[k] = g_pool[row * 64 + k];
    float h1[64];
    for (int j = 0; j < 64; j++) {
        float a = sb1[j];
        #pragma unroll
        for (int k = 0; k < 64; k++) a += gin[k] * s1[k * 64 + j];
        h1[j] = fmaxf(a, 0.f);
    }
    float h2[32];
    for (int j = 0; j < 32; j++) {
        float a = sb2[j];
        #pragma unroll
        for (int k = 0; k < 64; k++) a += h1[k] * s2[k * 32 + j];
        h2[j] = fmaxf(a, 0.f);
    }
    float h3[32];
    for (int j = 0; j < 32; j++) {
        float a = sb3[j];
        #pragma unroll
        for (int k = 0; k < 32; k++) a += h2[k] * s3[k * 32 + j];
        h3[j] = fmaxf(a, 0.f);
    }
    float o = sb4;
    #pragma unroll
    for (int k = 0; k < 32; k++) o += h3[k] * s4[k];
    out[row] = o;
}

// ---------------- host launch: KERNEL LAUNCHES ONLY ----------------
extern "C" void kernel_launch(void* const* d_in, const int* in_sizes, int n_in,
                              void* d_out, int out_size) {
    const float* x = (const float*)d_in[0];
    const void* ei = d_in[1];
    const void* batch = d_in[2];
    const float* c1wl = (const float*)d_in[3];
    const float* c1bl = (const float*)d_in[4];
    const float* c1wr = (const float*)d_in[5];
    const float* c2wl = (const float*)d_in[6];
    const float* c2bl = (const float*)d_in[7];
    const float* c2wr = (const float*)d_in[8];
    const float* c3wl = (const float*)d_in[9];
    const float* c3bl = (const float*)d_in[10];
    const float* c3wr = (const float*)d_in[11];
    const float* c4wl = (const float*)d_in[12];
    const float* c4bl = (const float*)d_in[13];
    const float* c4wr = (const float*)d_in[14];
    const float* l1w = (const float*)d_in[15];
    const float* l1b = (const float*)d_in[16];
    const float* l2w = (const float*)d_in[17];
    const float* l2b = (const float*)d_in[18];
    const float* l3w = (const float*)d_in[19];
    const float* l3b = (const float*)d_in[20];
    const float* l4w = (const float*)d_in[21];
    const float* l4b = (const float*)d_in[22];
    float* out = (float*)d_out;

    k_zero<<<(N_NODES + 255) / 256, 256>>>((const unsigned int*)ei);
    k_cvt_count<<<(N_EDGES + 255) / 256, 256>>>(ei, batch);
    k_x2h<<<(N_NODES * 16 + 255) / 256, 256>>>(x);
    k_scanA<<<SCAN_BLOCKS, 1024>>>();
    k_scanB<<<1, 1024>>>();
    k_scanC<<<(N_NODES + 1023) / 1024, 1024>>>();
    k_fill<<<(N_EDGES + 255) / 256, 256>>>();

    int aggBlocks = (N_NODES * 32 + 255) / 256;
    int gemmBlocks = (N_NODES + 127) / 128;

    // layer 1: aggx = mean(xh[src]); h1 = relu([aggx|x] @ [wl;wr] + b1)  (h1: [N,128] fp32)
    k_aggh<false, 0><<<aggBlocks, 256>>>(nullptr);
    k_gemm<128, true, true, 0, 1, false><<<gemmBlocks, 256>>>(nullptr, 64, x, c1wl, c1wr, c1bl);

    // layer 2: y = h1 @ [wl|wr] split(yh fp16, ys fp32); h2 = relu(mean(yh[src]) + b2 + ys)
    k_gemm<128, false, false, 1, 1, true><<<gemmBlocks, 256>>>(nullptr, 128, nullptr, c2wl, c2wr, nullptr);
    k_aggh<true, 1><<<aggBlocks, 256>>>(c2bl);

    // layer 3
    k_gemm<64, false, false, 1, 1, true><<<gemmBlocks, 256>>>(nullptr, 64, nullptr, c3wl, c3wr, nullptr);
    k_aggh<true, 1><<<aggBlocks, 256>>>(c3bl);

    // layer 4
    k_gemm<64, false, false, 1, 1, true><<<gemmBlocks, 256>>>(nullptr, 64, nullptr, c4wl, c4wr, nullptr);
    k_aggh<true, 1><<<aggBlocks, 256>>>(c4bl);

    // pool + MLP head
    k_pool<<<N_GRAPHS, 64>>>();
    k_mlp<<<(N_GRAPHS + 255) / 256, 256>>>(l1w, l1b, l2w, l2b, l3w, l3b, l4w, l4b, out);
}